// round 1
// baseline (speedup 1.0000x reference)
#include <cuda_runtime.h>
#include <math.h>

#define B_    8
#define S_    4096
#define DIN   512
#define DHID  1024
#define DOUT  512
#define M_    (B_ * S_)          // 32768 rows

// Scratch (allocation-free rule: __device__ globals)
__device__ float g_u[(size_t)M_ * DHID];   // gated input projection
__device__ float g_h[(size_t)M_ * DHID];   // scan output
__device__ float g_a[DHID];
__device__ float g_gate[DHID];

// ---------------------------------------------------------------------------
// Precompute a = sigmoid(a_logit), gate = sqrt(1 - a^2)
// ---------------------------------------------------------------------------
__global__ void precompute_kernel(const float* __restrict__ a_logit) {
    int d = blockIdx.x * blockDim.x + threadIdx.x;
    if (d < DHID) {
        float a = 1.0f / (1.0f + expf(-a_logit[d]));
        g_a[d] = a;
        g_gate[d] = sqrtf(fmaxf(1.0f - a * a, 0.0f));
    }
}

// ---------------------------------------------------------------------------
// SGEMM 1: g_u[m,n] = gate[n] * (X[m,:] @ W_in[:,n] + b_in[n])
// M=32768, N=1024, K=512.  128x128 tile, BK=16, 256 threads, 8x8 per thread.
// ---------------------------------------------------------------------------
__global__ __launch_bounds__(256) void gemm_u_kernel(
    const float* __restrict__ X,      // [M_, DIN]
    const float* __restrict__ W,      // [DIN, DHID]
    const float* __restrict__ bias)   // [DHID]
{
    __shared__ float As[16][128];     // As[k][m]
    __shared__ float Bs[16][128];     // Bs[k][n]

    const int tid = threadIdx.x;
    const int bm = blockIdx.y * 128;
    const int bn = blockIdx.x * 128;
    const int tm = (tid / 16) * 8;
    const int tn = (tid % 16) * 8;

    float acc[8][8];
#pragma unroll
    for (int i = 0; i < 8; i++)
#pragma unroll
        for (int j = 0; j < 8; j++) acc[i][j] = 0.0f;

    for (int k0 = 0; k0 < DIN; k0 += 16) {
        // Load A tile (128 rows x 16 k), transposed into As[k][m]
#pragma unroll
        for (int i = 0; i < 2; i++) {
            int f = tid + i * 256;            // 0..511 float4 slots
            int row = f >> 2;
            int kc4 = (f & 3) * 4;
            float4 v = *(const float4*)(X + (size_t)(bm + row) * DIN + k0 + kc4);
            As[kc4 + 0][row] = v.x;
            As[kc4 + 1][row] = v.y;
            As[kc4 + 2][row] = v.z;
            As[kc4 + 3][row] = v.w;
        }
        // Load B tile (16 k x 128 n)
#pragma unroll
        for (int i = 0; i < 2; i++) {
            int f = tid + i * 256;
            int kr = f >> 5;
            int nc4 = (f & 31) * 4;
            *(float4*)(&Bs[kr][nc4]) =
                *(const float4*)(W + (size_t)(k0 + kr) * DHID + bn + nc4);
        }
        __syncthreads();

#pragma unroll
        for (int kk = 0; kk < 16; kk++) {
            float a[8], b[8];
            *(float4*)(a)     = *(const float4*)(&As[kk][tm]);
            *(float4*)(a + 4) = *(const float4*)(&As[kk][tm + 4]);
            *(float4*)(b)     = *(const float4*)(&Bs[kk][tn]);
            *(float4*)(b + 4) = *(const float4*)(&Bs[kk][tn + 4]);
#pragma unroll
            for (int i = 0; i < 8; i++)
#pragma unroll
                for (int j = 0; j < 8; j++)
                    acc[i][j] = fmaf(a[i], b[j], acc[i][j]);
        }
        __syncthreads();
    }

#pragma unroll
    for (int i = 0; i < 8; i++) {
        int m = bm + tm + i;
#pragma unroll
        for (int j = 0; j < 8; j++) {
            int n = bn + tn + j;
            g_u[(size_t)m * DHID + n] = g_gate[n] * (acc[i][j] + bias[n]);
        }
    }
}

// ---------------------------------------------------------------------------
// Scan: h_t = a * h_{t-1} + u_t  per channel (b, d). One thread per channel.
// Also writes h_last into the tail of d_out.
// ---------------------------------------------------------------------------
__global__ __launch_bounds__(256) void scan_kernel(
    const float* __restrict__ h0, float* __restrict__ out)
{
    int idx = blockIdx.x * blockDim.x + threadIdx.x;   // 0..8191
    int b = idx >> 10;
    int d = idx & 1023;

    float a = g_a[d];
    float h = h0[idx];
    const float* up = g_u + (size_t)b * S_ * DHID + d;
    float* hp = g_h + (size_t)b * S_ * DHID + d;

#pragma unroll 8
    for (int t = 0; t < S_; t++) {
        h = fmaf(a, h, up[(size_t)t * DHID]);
        hp[(size_t)t * DHID] = h;
    }
    // h_last goes after the (B,S,DOUT) output block
    out[(size_t)M_ * DOUT + idx] = h;
}

// ---------------------------------------------------------------------------
// SGEMM 2 (fused): out[m,o] = 0.5*( X@W_dx + g_h@W_out + b_dx[o] + b_out[o] )
// M=32768, N=512, K1=512 (X,W_dx) then K2=1024 (g_h,W_out).
// ---------------------------------------------------------------------------
__global__ __launch_bounds__(256) void gemm_out_kernel(
    const float* __restrict__ X,      // [M_, DIN]
    const float* __restrict__ Wdx,    // [DIN, DOUT]
    const float* __restrict__ bdx,    // [DOUT]
    const float* __restrict__ Wout,   // [DHID, DOUT]
    const float* __restrict__ bout,   // [DOUT]
    float* __restrict__ out)          // [M_, DOUT]
{
    __shared__ float As[16][128];
    __shared__ float Bs[16][128];

    const int tid = threadIdx.x;
    const int bm = blockIdx.y * 128;
    const int bn = blockIdx.x * 128;
    const int tm = (tid / 16) * 8;
    const int tn = (tid % 16) * 8;

    float acc[8][8];
#pragma unroll
    for (int i = 0; i < 8; i++)
#pragma unroll
        for (int j = 0; j < 8; j++) acc[i][j] = 0.0f;

    // Phase selects (A, lda, B, K)
    for (int phase = 0; phase < 2; phase++) {
        const float* A   = (phase == 0) ? X    : g_h;
        const float* Bmat= (phase == 0) ? Wdx  : Wout;
        const int lda    = (phase == 0) ? DIN  : DHID;
        const int K      = (phase == 0) ? DIN  : DHID;

        for (int k0 = 0; k0 < K; k0 += 16) {
#pragma unroll
            for (int i = 0; i < 2; i++) {
                int f = tid + i * 256;
                int row = f >> 2;
                int kc4 = (f & 3) * 4;
                float4 v = *(const float4*)(A + (size_t)(bm + row) * lda + k0 + kc4);
                As[kc4 + 0][row] = v.x;
                As[kc4 + 1][row] = v.y;
                As[kc4 + 2][row] = v.z;
                As[kc4 + 3][row] = v.w;
            }
#pragma unroll
            for (int i = 0; i < 2; i++) {
                int f = tid + i * 256;
                int kr = f >> 5;
                int nc4 = (f & 31) * 4;
                *(float4*)(&Bs[kr][nc4]) =
                    *(const float4*)(Bmat + (size_t)(k0 + kr) * DOUT + bn + nc4);
            }
            __syncthreads();

#pragma unroll
            for (int kk = 0; kk < 16; kk++) {
                float a[8], b[8];
                *(float4*)(a)     = *(const float4*)(&As[kk][tm]);
                *(float4*)(a + 4) = *(const float4*)(&As[kk][tm + 4]);
                *(float4*)(b)     = *(const float4*)(&Bs[kk][tn]);
                *(float4*)(b + 4) = *(const float4*)(&Bs[kk][tn + 4]);
#pragma unroll
                for (int i = 0; i < 8; i++)
#pragma unroll
                    for (int j = 0; j < 8; j++)
                        acc[i][j] = fmaf(a[i], b[j], acc[i][j]);
            }
            __syncthreads();
        }
    }

#pragma unroll
    for (int i = 0; i < 8; i++) {
        int m = bm + tm + i;
#pragma unroll
        for (int j = 0; j < 8; j++) {
            int n = bn + tn + j;
            out[(size_t)m * DOUT + n] =
                0.5f * (acc[i][j] + bdx[n] + bout[n]);
        }
    }
}

// ---------------------------------------------------------------------------
extern "C" void kernel_launch(void* const* d_in, const int* in_sizes, int n_in,
                              void* d_out, int out_size)
{
    const float* x       = (const float*)d_in[0];
    const float* h0      = (const float*)d_in[1];
    const float* a_logit = (const float*)d_in[2];
    const float* W_dx    = (const float*)d_in[3];
    const float* b_dx    = (const float*)d_in[4];
    const float* W_in    = (const float*)d_in[5];
    const float* b_in    = (const float*)d_in[6];
    const float* W_out   = (const float*)d_in[7];
    const float* b_out   = (const float*)d_in[8];
    float* out = (float*)d_out;

    precompute_kernel<<<1, 1024>>>(a_logit);
    gemm_u_kernel<<<dim3(DHID / 128, M_ / 128), 256>>>(x, W_in, b_in);
    scan_kernel<<<(B_ * DHID) / 256, 256>>>(h0, out);
    gemm_out_kernel<<<dim3(DOUT / 128, M_ / 128), 256>>>(x, W_dx, b_dx,
                                                         W_out, b_out, out);
}

// round 3
// speedup vs baseline: 1.7513x; 1.7513x over previous
#include <cuda_runtime.h>
#include <cuda_fp16.h>
#include <math.h>
#include <stdint.h>

#define B_    8
#define S_    4096
#define DIN   512
#define DHID  1024
#define DOUT  512
#define M_    (B_ * S_)          // 32768 rows

// ---------------------------------------------------------------------------
// Scratch (__device__ globals: allocation-free rule)
// ---------------------------------------------------------------------------
__device__ float  g_a[DHID];
__device__ float  g_gate[DHID];
__device__ __half g_x16[(size_t)M_ * DIN];        // x in fp16
__device__ __half g_u16[(size_t)M_ * DHID];       // gated input proj (fp16)
__device__ __half g_h16[(size_t)M_ * DHID];       // scan states (fp16)
__device__ __half g_winT16[DHID * DIN];           // W_in^T  [n=1024][k=512]
__device__ __half g_wdxT16[DOUT * DIN];           // W_dx^T  [n=512][k=512]
__device__ __half g_woutT16[DOUT * DHID];         // W_out^T [n=512][k=1024]

// ---------------------------------------------------------------------------
// PTX helpers (baseline sm_80+ instructions only — no 'a' features)
// ---------------------------------------------------------------------------
__device__ __forceinline__ uint32_t smem_u32(const void* p) {
    uint32_t a;
    asm("{ .reg .u64 t; cvta.to.shared.u64 t, %1; cvt.u32.u64 %0, t; }"
        : "=r"(a) : "l"(p));
    return a;
}

__device__ __forceinline__ void cp_async16(uint32_t saddr, const void* gptr) {
    asm volatile("cp.async.cg.shared.global [%0], [%1], 16;"
                 :: "r"(saddr), "l"(gptr));
}
#define CP_COMMIT() asm volatile("cp.async.commit_group;" ::: "memory")
#define CP_WAIT(n)  asm volatile("cp.async.wait_group %0;" :: "n"(n) : "memory")

__device__ __forceinline__ void ldsm_x4(uint32_t& r0, uint32_t& r1,
                                        uint32_t& r2, uint32_t& r3, uint32_t addr) {
    asm volatile("ldmatrix.sync.aligned.m8n8.x4.shared.b16 {%0,%1,%2,%3}, [%4];"
                 : "=r"(r0), "=r"(r1), "=r"(r2), "=r"(r3) : "r"(addr));
}

__device__ __forceinline__ void mma_16816(float* d, const uint32_t* a,
                                          uint32_t b0, uint32_t b1) {
    asm volatile("mma.sync.aligned.m16n8k16.row.col.f32.f16.f16.f32 "
                 "{%0,%1,%2,%3}, {%4,%5,%6,%7}, {%8,%9}, {%0,%1,%2,%3};"
                 : "+f"(d[0]), "+f"(d[1]), "+f"(d[2]), "+f"(d[3])
                 : "r"(a[0]), "r"(a[1]), "r"(a[2]), "r"(a[3]), "r"(b0), "r"(b1));
}

// ---------------------------------------------------------------------------
// SMEM tile layout: 128 rows x 64 halves, row stride padded to 144B.
// 16B-unit index 9r+u mod 8 distinct over 8 rows -> conflict-free ldmatrix.
// ---------------------------------------------------------------------------
#define ROWB     144
#define TILE_B   (128 * ROWB)         // 18432
#define STAGE_B  (2 * TILE_B)         // A + B tile
#define SMEM_TOT (2 * STAGE_B)        // double buffer = 73728

__device__ __forceinline__ void load_stage_async(uint32_t s_base,
    const __half* __restrict__ A, int lda, int am0, int ak0,
    const __half* __restrict__ Bm, int ldb, int bn0, int bk0)
{
    const int tid = threadIdx.x;
#pragma unroll
    for (int i = 0; i < 4; i++) {
        int id  = tid + i * 256;      // 0..1023
        int row = id >> 3;
        int u   = id & 7;
        cp_async16(s_base + row * ROWB + u * 16,
                   A + (size_t)(am0 + row) * lda + ak0 + u * 8);
        cp_async16(s_base + TILE_B + row * ROWB + u * 16,
                   Bm + (size_t)(bn0 + row) * ldb + bk0 + u * 8);
    }
}

__device__ __forceinline__ void compute_stage(uint32_t s_base,
    float acc[2][8][4], int warp_m, int warp_n, int lane)
{
    const uint32_t aB = s_base;
    const uint32_t bB = s_base + TILE_B;
#pragma unroll
    for (int ks = 0; ks < 4; ks++) {
        uint32_t a[2][4];
#pragma unroll
        for (int im = 0; im < 2; im++) {
            int row  = warp_m * 32 + im * 16 + (lane & 7) + ((lane >> 3) & 1) * 8;
            int unit = ks * 2 + (lane >> 4);
            ldsm_x4(a[im][0], a[im][1], a[im][2], a[im][3],
                    aB + row * ROWB + unit * 16);
        }
        uint32_t b[4][4];
#pragma unroll
        for (int jn = 0; jn < 4; jn++) {
            int row  = warp_n * 64 + jn * 16 + (lane & 7) + ((lane >> 4) & 1) * 8;
            int unit = ks * 2 + ((lane >> 3) & 1);
            ldsm_x4(b[jn][0], b[jn][1], b[jn][2], b[jn][3],
                    bB + row * ROWB + unit * 16);
        }
#pragma unroll
        for (int im = 0; im < 2; im++)
#pragma unroll
            for (int jn = 0; jn < 4; jn++) {
                mma_16816(acc[im][jn * 2 + 0], a[im], b[jn][0], b[jn][1]);
                mma_16816(acc[im][jn * 2 + 1], a[im], b[jn][2], b[jn][3]);
            }
    }
}

// ---------------------------------------------------------------------------
// Pre/conversion kernels
// ---------------------------------------------------------------------------
__global__ void precompute_kernel(const float* __restrict__ a_logit) {
    int d = blockIdx.x * blockDim.x + threadIdx.x;
    if (d < DHID) {
        float a = 1.0f / (1.0f + expf(-a_logit[d]));
        g_a[d] = a;
        g_gate[d] = sqrtf(fmaxf(1.0f - a * a, 0.0f));
    }
}

__global__ __launch_bounds__(256) void convert_x_kernel(const float* __restrict__ x) {
    size_t i = ((size_t)blockIdx.x * 256 + threadIdx.x) * 8;
    float4 v0 = *(const float4*)(x + i);
    float4 v1 = *(const float4*)(x + i + 4);
    __half2 h0 = __floats2half2_rn(v0.x, v0.y);
    __half2 h1 = __floats2half2_rn(v0.z, v0.w);
    __half2 h2 = __floats2half2_rn(v1.x, v1.y);
    __half2 h3 = __floats2half2_rn(v1.z, v1.w);
    *(__half2*)(g_x16 + i + 0) = h0;
    *(__half2*)(g_x16 + i + 2) = h1;
    *(__half2*)(g_x16 + i + 4) = h2;
    *(__half2*)(g_x16 + i + 6) = h3;
}

// W[K][N] fp32 -> T[N][K] fp16
__global__ void transpose_convert_kernel(const float* __restrict__ W, int which,
                                         int K, int N) {
    __shared__ float t[32][33];
    __half* T = (which == 0) ? g_winT16 : (which == 1) ? g_wdxT16 : g_woutT16;
    int n0 = blockIdx.x * 32, k0 = blockIdx.y * 32;
    int tx = threadIdx.x, ty = threadIdx.y;   // (32, 8)
#pragma unroll
    for (int i = 0; i < 4; i++)
        t[ty + i * 8][tx] = W[(size_t)(k0 + ty + i * 8) * N + n0 + tx];
    __syncthreads();
#pragma unroll
    for (int i = 0; i < 4; i++)
        T[(size_t)(n0 + ty + i * 8) * K + k0 + tx] = __float2half_rn(t[tx][ty + i * 8]);
}

// ---------------------------------------------------------------------------
// GEMM 1: u[m,n] = gate[n] * (x @ W_in + b_in)   -> g_u16
// ---------------------------------------------------------------------------
__global__ __launch_bounds__(256, 1) void gemm_u_mma(const float* __restrict__ bias) {
    extern __shared__ char smem[];
    const uint32_t sb = smem_u32(smem);
    const int tid = threadIdx.x, wid = tid >> 5, lane = tid & 31;
    const int warp_m = wid >> 1, warp_n = wid & 1;
    const int bn = blockIdx.x * 128, bm = blockIdx.y * 128;

    float acc[2][8][4];
#pragma unroll
    for (int i = 0; i < 2; i++)
#pragma unroll
        for (int j = 0; j < 8; j++)
#pragma unroll
            for (int r = 0; r < 4; r++) acc[i][j][r] = 0.0f;

    load_stage_async(sb, g_x16, DIN, bm, 0, g_winT16, DIN, bn, 0);
    CP_COMMIT();

    const int NC = DIN / 64;     // 8
    for (int c = 0; c < NC; c++) {
        uint32_t cur = sb + (c & 1) * STAGE_B;
        if (c + 1 < NC) {
            load_stage_async(sb + ((c + 1) & 1) * STAGE_B,
                             g_x16, DIN, bm, (c + 1) * 64,
                             g_winT16, DIN, bn, (c + 1) * 64);
            CP_COMMIT();
            CP_WAIT(1);
        } else {
            CP_WAIT(0);
        }
        __syncthreads();
        compute_stage(cur, acc, warp_m, warp_n, lane);
        __syncthreads();
    }

    const int rw = lane >> 2, cq = lane & 3;
#pragma unroll
    for (int im = 0; im < 2; im++) {
        int m0 = bm + warp_m * 32 + im * 16 + rw;
#pragma unroll
        for (int jf = 0; jf < 8; jf++) {
            int n = bn + warp_n * 64 + jf * 8 + cq * 2;
            float g0 = g_gate[n], g1 = g_gate[n + 1];
            float b0 = bias[n],   b1 = bias[n + 1];
            float* a4 = acc[im][jf];
            *(__half2*)(g_u16 + (size_t)m0 * DHID + n) =
                __floats2half2_rn(g0 * (a4[0] + b0), g1 * (a4[1] + b1));
            *(__half2*)(g_u16 + (size_t)(m0 + 8) * DHID + n) =
                __floats2half2_rn(g0 * (a4[2] + b0), g1 * (a4[3] + b1));
        }
    }
}

// ---------------------------------------------------------------------------
// Scan: h_t = a*h_{t-1} + u_t (fp32 math, fp16 IO); h_last -> out tail
// ---------------------------------------------------------------------------
__global__ __launch_bounds__(256) void scan_kernel(
    const float* __restrict__ h0, float* __restrict__ out)
{
    int idx = blockIdx.x * blockDim.x + threadIdx.x;   // 0..8191
    int b = idx >> 10;
    int d = idx & 1023;

    float a = g_a[d];
    float h = h0[idx];
    const __half* up = g_u16 + (size_t)b * S_ * DHID + d;
    __half* hp = g_h16 + (size_t)b * S_ * DHID + d;

#pragma unroll 8
    for (int t = 0; t < S_; t++) {
        h = fmaf(a, h, __half2float(up[(size_t)t * DHID]));
        hp[(size_t)t * DHID] = __float2half_rn(h);
    }
    out[(size_t)M_ * DOUT + idx] = h;
}

// ---------------------------------------------------------------------------
// GEMM 2 (fused): out = 0.5*(x@W_dx + h@W_out + b_dx + b_out)
// 24 K-chunks: 8 of (x, W_dx^T) then 16 of (h, W_out^T).
// ---------------------------------------------------------------------------
__device__ __forceinline__ void load_chunk2(uint32_t s_base, int c, int bm, int bn) {
    if (c < 8)
        load_stage_async(s_base, g_x16, DIN, bm, c * 64, g_wdxT16, DIN, bn, c * 64);
    else
        load_stage_async(s_base, g_h16, DHID, bm, (c - 8) * 64,
                         g_woutT16, DHID, bn, (c - 8) * 64);
}

__global__ __launch_bounds__(256, 1) void gemm_out_mma(
    const float* __restrict__ bdx, const float* __restrict__ bout,
    float* __restrict__ out)
{
    extern __shared__ char smem[];
    const uint32_t sb = smem_u32(smem);
    const int tid = threadIdx.x, wid = tid >> 5, lane = tid & 31;
    const int warp_m = wid >> 1, warp_n = wid & 1;
    const int bn = blockIdx.x * 128, bm = blockIdx.y * 128;

    float acc[2][8][4];
#pragma unroll
    for (int i = 0; i < 2; i++)
#pragma unroll
        for (int j = 0; j < 8; j++)
#pragma unroll
            for (int r = 0; r < 4; r++) acc[i][j][r] = 0.0f;

    load_chunk2(sb, 0, bm, bn);
    CP_COMMIT();

    const int NC = 24;
    for (int c = 0; c < NC; c++) {
        uint32_t cur = sb + (c & 1) * STAGE_B;
        if (c + 1 < NC) {
            load_chunk2(sb + ((c + 1) & 1) * STAGE_B, c + 1, bm, bn);
            CP_COMMIT();
            CP_WAIT(1);
        } else {
            CP_WAIT(0);
        }
        __syncthreads();
        compute_stage(cur, acc, warp_m, warp_n, lane);
        __syncthreads();
    }

    const int rw = lane >> 2, cq = lane & 3;
#pragma unroll
    for (int im = 0; im < 2; im++) {
        int m0 = bm + warp_m * 32 + im * 16 + rw;
#pragma unroll
        for (int jf = 0; jf < 8; jf++) {
            int n = bn + warp_n * 64 + jf * 8 + cq * 2;
            float b0 = bdx[n] + bout[n], b1 = bdx[n + 1] + bout[n + 1];
            float* a4 = acc[im][jf];
            float2 v0 = make_float2(0.5f * (a4[0] + b0), 0.5f * (a4[1] + b1));
            float2 v1 = make_float2(0.5f * (a4[2] + b0), 0.5f * (a4[3] + b1));
            *(float2*)(out + (size_t)m0 * DOUT + n) = v0;
            *(float2*)(out + (size_t)(m0 + 8) * DOUT + n) = v1;
        }
    }
}

// ---------------------------------------------------------------------------
extern "C" void kernel_launch(void* const* d_in, const int* in_sizes, int n_in,
                              void* d_out, int out_size)
{
    const float* x       = (const float*)d_in[0];
    const float* h0      = (const float*)d_in[1];
    const float* a_logit = (const float*)d_in[2];
    const float* W_dx    = (const float*)d_in[3];
    const float* b_dx    = (const float*)d_in[4];
    const float* W_in    = (const float*)d_in[5];
    const float* b_in    = (const float*)d_in[6];
    const float* W_out   = (const float*)d_in[7];
    const float* b_out   = (const float*)d_in[8];
    float* out = (float*)d_out;

    cudaFuncSetAttribute(gemm_u_mma,   cudaFuncAttributeMaxDynamicSharedMemorySize, SMEM_TOT);
    cudaFuncSetAttribute(gemm_out_mma, cudaFuncAttributeMaxDynamicSharedMemorySize, SMEM_TOT);

    precompute_kernel<<<1, 1024>>>(a_logit);
    convert_x_kernel<<<(int)((size_t)M_ * DIN / 8 / 256), 256>>>(x);
    transpose_convert_kernel<<<dim3(DHID / 32, DIN / 32),  dim3(32, 8)>>>(W_in,  0, DIN,  DHID);
    transpose_convert_kernel<<<dim3(DOUT / 32, DIN / 32),  dim3(32, 8)>>>(W_dx,  1, DIN,  DOUT);
    transpose_convert_kernel<<<dim3(DOUT / 32, DHID / 32), dim3(32, 8)>>>(W_out, 2, DHID, DOUT);

    gemm_u_mma<<<dim3(DHID / 128, M_ / 128), 256, SMEM_TOT>>>(b_in);
    scan_kernel<<<(B_ * DHID) / 256, 256>>>(h0, out);
    gemm_out_mma<<<dim3(DOUT / 128, M_ / 128), 256, SMEM_TOT>>>(b_dx, b_out, out);
}

// round 5
// speedup vs baseline: 11.4498x; 6.5380x over previous
#include <cuda_runtime.h>
#include <cuda_fp16.h>
#include <math.h>
#include <stdint.h>

#define B_    8
#define S_    4096
#define DIN   512
#define DHID  1024
#define DOUT  512
#define M_    (B_ * S_)          // 32768 rows
#define LCH   128                // scan chunk length
#define NCH   (S_ / LCH)         // 32 chunks

// ---------------------------------------------------------------------------
// Scratch (__device__ globals)
// ---------------------------------------------------------------------------
__device__ float  g_a[DHID];
__device__ float  g_gate[DHID];
__device__ __half g_x16[(size_t)M_ * DIN];
__device__ __half g_u16[(size_t)M_ * DHID];
__device__ __half g_h16[(size_t)M_ * DHID];
__device__ float  g_part[(size_t)B_ * NCH * DHID];   // chunk local-scan ends
__device__ float  g_carry[(size_t)B_ * NCH * DHID];  // h at chunk starts
__device__ __half g_winT16[DHID * DIN];
__device__ __half g_wdxT16[DOUT * DIN];
__device__ __half g_woutT16[DOUT * DHID];

// ---------------------------------------------------------------------------
// PTX helpers (baseline sm_80+ only)
// ---------------------------------------------------------------------------
__device__ __forceinline__ uint32_t smem_u32(const void* p) {
    uint32_t a;
    asm("{ .reg .u64 t; cvta.to.shared.u64 t, %1; cvt.u32.u64 %0, t; }"
        : "=r"(a) : "l"(p));
    return a;
}
__device__ __forceinline__ void cp_async16(uint32_t saddr, const void* gptr) {
    asm volatile("cp.async.cg.shared.global [%0], [%1], 16;"
                 :: "r"(saddr), "l"(gptr));
}
#define CP_COMMIT() asm volatile("cp.async.commit_group;" ::: "memory")
#define CP_WAIT(n)  asm volatile("cp.async.wait_group %0;" :: "n"(n) : "memory")

__device__ __forceinline__ void ldsm_x4(uint32_t& r0, uint32_t& r1,
                                        uint32_t& r2, uint32_t& r3, uint32_t addr) {
    asm volatile("ldmatrix.sync.aligned.m8n8.x4.shared.b16 {%0,%1,%2,%3}, [%4];"
                 : "=r"(r0), "=r"(r1), "=r"(r2), "=r"(r3) : "r"(addr));
}
__device__ __forceinline__ void mma_16816(float* d, const uint32_t* a,
                                          uint32_t b0, uint32_t b1) {
    asm volatile("mma.sync.aligned.m16n8k16.row.col.f32.f16.f16.f32 "
                 "{%0,%1,%2,%3}, {%4,%5,%6,%7}, {%8,%9}, {%0,%1,%2,%3};"
                 : "+f"(d[0]), "+f"(d[1]), "+f"(d[2]), "+f"(d[3])
                 : "r"(a[0]), "r"(a[1]), "r"(a[2]), "r"(a[3]), "r"(b0), "r"(b1));
}

// ---------------------------------------------------------------------------
// SMEM tiles: 128 rows x 64 halves = 128B/row with XOR swizzle (16B unit
// column = u ^ (row & 7)) -> conflict-free cp.async stores + ldmatrix loads.
// ---------------------------------------------------------------------------
#define ROWB     128
#define TILE_B   (128 * ROWB)         // 16384
#define STAGE_B  (2 * TILE_B)         // A + B tile = 32768
#define SMEM_TOT (2 * STAGE_B)        // double buffer = 65536

__device__ __forceinline__ void load_stage_async(uint32_t s_base,
    const __half* __restrict__ A, int lda, int am0, int ak0,
    const __half* __restrict__ Bm, int ldb, int bn0, int bk0)
{
    const int tid = threadIdx.x;
#pragma unroll
    for (int i = 0; i < 4; i++) {
        int id  = tid + i * 256;      // 0..1023
        int row = id >> 3;
        int u   = id & 7;
        int su  = (u ^ (row & 7)) * 16;
        cp_async16(s_base + row * ROWB + su,
                   A + (size_t)(am0 + row) * lda + ak0 + u * 8);
        cp_async16(s_base + TILE_B + row * ROWB + su,
                   Bm + (size_t)(bn0 + row) * ldb + bk0 + u * 8);
    }
}

__device__ __forceinline__ void compute_stage(uint32_t s_base,
    float acc[2][8][4], int warp_m, int warp_n, int lane)
{
    const uint32_t aB = s_base;
    const uint32_t bB = s_base + TILE_B;
#pragma unroll
    for (int ks = 0; ks < 4; ks++) {
        uint32_t a[2][4];
#pragma unroll
        for (int im = 0; im < 2; im++) {
            int row  = warp_m * 32 + im * 16 + (lane & 7) + ((lane >> 3) & 1) * 8;
            int unit = ks * 2 + (lane >> 4);
            ldsm_x4(a[im][0], a[im][1], a[im][2], a[im][3],
                    aB + row * ROWB + ((unit ^ (row & 7)) * 16));
        }
        uint32_t b[4][4];
#pragma unroll
        for (int jn = 0; jn < 4; jn++) {
            int row  = warp_n * 64 + jn * 16 + (lane & 7) + ((lane >> 4) & 1) * 8;
            int unit = ks * 2 + ((lane >> 3) & 1);
            ldsm_x4(b[jn][0], b[jn][1], b[jn][2], b[jn][3],
                    bB + row * ROWB + ((unit ^ (row & 7)) * 16));
        }
#pragma unroll
        for (int im = 0; im < 2; im++)
#pragma unroll
            for (int jn = 0; jn < 4; jn++) {
                mma_16816(acc[im][jn * 2 + 0], a[im], b[jn][0], b[jn][1]);
                mma_16816(acc[im][jn * 2 + 1], a[im], b[jn][2], b[jn][3]);
            }
    }
}

// ---------------------------------------------------------------------------
// Pre/conversion kernels
// ---------------------------------------------------------------------------
__global__ void precompute_kernel(const float* __restrict__ a_logit) {
    int d = blockIdx.x * blockDim.x + threadIdx.x;
    if (d < DHID) {
        float a = 1.0f / (1.0f + expf(-a_logit[d]));
        g_a[d] = a;
        g_gate[d] = sqrtf(fmaxf(1.0f - a * a, 0.0f));
    }
}

__global__ __launch_bounds__(256) void convert_x_kernel(const float* __restrict__ x) {
    size_t i = ((size_t)blockIdx.x * 256 + threadIdx.x) * 8;
    float4 v0 = *(const float4*)(x + i);
    float4 v1 = *(const float4*)(x + i + 4);
    *(__half2*)(g_x16 + i + 0) = __floats2half2_rn(v0.x, v0.y);
    *(__half2*)(g_x16 + i + 2) = __floats2half2_rn(v0.z, v0.w);
    *(__half2*)(g_x16 + i + 4) = __floats2half2_rn(v1.x, v1.y);
    *(__half2*)(g_x16 + i + 6) = __floats2half2_rn(v1.z, v1.w);
}

// All 3 weight transposes in ONE launch. Flattened block index:
//  [0,512):    W_in  (K=512, N=1024)
//  [512,768):  W_dx  (K=512, N=512)
//  [768,1280): W_out (K=1024, N=512)
__global__ void transpose_all_kernel(const float* __restrict__ Win,
                                     const float* __restrict__ Wdx,
                                     const float* __restrict__ Wout) {
    __shared__ float t[32][33];
    int bid = blockIdx.x;
    const float* W; __half* T; int K, N, nb;
    if (bid < 512)      { W = Win;  T = g_winT16;  K = DIN;  N = DHID; nb = 32; }
    else if (bid < 768) { W = Wdx;  T = g_wdxT16;  K = DIN;  N = DOUT; nb = 16; bid -= 512; }
    else                { W = Wout; T = g_woutT16; K = DHID; N = DOUT; nb = 16; bid -= 768; }
    int n0 = (bid % nb) * 32, k0 = (bid / nb) * 32;
    int tx = threadIdx.x, ty = threadIdx.y;   // (32, 8)
#pragma unroll
    for (int i = 0; i < 4; i++)
        t[ty + i * 8][tx] = W[(size_t)(k0 + ty + i * 8) * N + n0 + tx];
    __syncthreads();
#pragma unroll
    for (int i = 0; i < 4; i++)
        T[(size_t)(n0 + ty + i * 8) * K + k0 + tx] = __float2half_rn(t[tx][ty + i * 8]);
}

// ---------------------------------------------------------------------------
// GEMM 1: u[m,n] = gate[n] * (x @ W_in + b_in)  -> g_u16
// ---------------------------------------------------------------------------
__global__ __launch_bounds__(256) void gemm_u_mma(const float* __restrict__ bias) {
    extern __shared__ char smem[];
    const uint32_t sb = smem_u32(smem);
    const int tid = threadIdx.x, wid = tid >> 5, lane = tid & 31;
    const int warp_m = wid >> 1, warp_n = wid & 1;
    const int bn = blockIdx.x * 128, bm = blockIdx.y * 128;

    float acc[2][8][4];
#pragma unroll
    for (int i = 0; i < 2; i++)
#pragma unroll
        for (int j = 0; j < 8; j++)
#pragma unroll
            for (int r = 0; r < 4; r++) acc[i][j][r] = 0.0f;

    load_stage_async(sb, g_x16, DIN, bm, 0, g_winT16, DIN, bn, 0);
    CP_COMMIT();

    const int NC = DIN / 64;     // 8
    for (int c = 0; c < NC; c++) {
        uint32_t cur = sb + (c & 1) * STAGE_B;
        if (c + 1 < NC) {
            load_stage_async(sb + ((c + 1) & 1) * STAGE_B,
                             g_x16, DIN, bm, (c + 1) * 64,
                             g_winT16, DIN, bn, (c + 1) * 64);
            CP_COMMIT();
            CP_WAIT(1);
        } else {
            CP_WAIT(0);
        }
        __syncthreads();
        compute_stage(cur, acc, warp_m, warp_n, lane);
        __syncthreads();
    }

    const int rw = lane >> 2, cq = lane & 3;
#pragma unroll
    for (int im = 0; im < 2; im++) {
        int m0 = bm + warp_m * 32 + im * 16 + rw;
#pragma unroll
        for (int jf = 0; jf < 8; jf++) {
            int n = bn + warp_n * 64 + jf * 8 + cq * 2;
            float g0 = g_gate[n], g1 = g_gate[n + 1];
            float b0 = bias[n],   b1 = bias[n + 1];
            float* a4 = acc[im][jf];
            *(__half2*)(g_u16 + (size_t)m0 * DHID + n) =
                __floats2half2_rn(g0 * (a4[0] + b0), g1 * (a4[1] + b1));
            *(__half2*)(g_u16 + (size_t)(m0 + 8) * DHID + n) =
                __floats2half2_rn(g0 * (a4[2] + b0), g1 * (a4[3] + b1));
        }
    }
}

// ---------------------------------------------------------------------------
// Chunked parallel scan (a constant per channel -> chunk decay = a^LCH)
// ---------------------------------------------------------------------------
// Phase A: local scan (zero init) per (b, chunk, d): end value -> g_part
__global__ __launch_bounds__(256) void scan_phaseA() {
    int d = blockIdx.x * 256 + threadIdx.x;      // 0..1023 (4 blocks)
    int c = blockIdx.y, b = blockIdx.z;
    float a = g_a[d];
    const __half* up = g_u16 + ((size_t)(b * S_ + c * LCH)) * DHID + d;
    float v = 0.0f;
#pragma unroll 8
    for (int t = 0; t < LCH; t++)
        v = fmaf(a, v, __half2float(up[(size_t)t * DHID]));
    g_part[((size_t)b * NCH + c) * DHID + d] = v;
}

// Phase B: scan 32 chunk carries per channel; write carries + h_last
__global__ __launch_bounds__(256) void scan_phaseB(
    const float* __restrict__ h0, float* __restrict__ out) {
    int idx = blockIdx.x * 256 + threadIdx.x;    // 0..8191
    int b = idx >> 10, d = idx & 1023;
    float a = g_a[d];
    float aL = a;                                 // a^128 via 7 squarings
#pragma unroll
    for (int i = 0; i < 7; i++) aL = aL * aL;
    float carry = h0[idx];
    const float* part = g_part + (size_t)b * NCH * DHID + d;
    float* cr = g_carry + (size_t)b * NCH * DHID + d;
#pragma unroll
    for (int c = 0; c < NCH; c++) {
        cr[(size_t)c * DHID] = carry;
        carry = fmaf(aL, carry, part[(size_t)c * DHID]);
    }
    out[(size_t)M_ * DOUT + idx] = carry;         // h_last
}

// Phase C: re-scan each chunk from its carry; write h (fp16)
__global__ __launch_bounds__(256) void scan_phaseC() {
    int d = blockIdx.x * 256 + threadIdx.x;
    int c = blockIdx.y, b = blockIdx.z;
    float a = g_a[d];
    float h = g_carry[((size_t)b * NCH + c) * DHID + d];
    const __half* up = g_u16 + ((size_t)(b * S_ + c * LCH)) * DHID + d;
    __half* hp = g_h16 + ((size_t)(b * S_ + c * LCH)) * DHID + d;
#pragma unroll 8
    for (int t = 0; t < LCH; t++) {
        h = fmaf(a, h, __half2float(up[(size_t)t * DHID]));
        hp[(size_t)t * DHID] = __float2half_rn(h);
    }
}

// ---------------------------------------------------------------------------
// GEMM 2 (fused): out = 0.5*(x@W_dx + h@W_out + b_dx + b_out)
// ---------------------------------------------------------------------------
__device__ __forceinline__ void load_chunk2(uint32_t s_base, int c, int bm, int bn) {
    if (c < 8)
        load_stage_async(s_base, g_x16, DIN, bm, c * 64, g_wdxT16, DIN, bn, c * 64);
    else
        load_stage_async(s_base, g_h16, DHID, bm, (c - 8) * 64,
                         g_woutT16, DHID, bn, (c - 8) * 64);
}

__global__ __launch_bounds__(256) void gemm_out_mma(
    const float* __restrict__ bdx, const float* __restrict__ bout,
    float* __restrict__ out)
{
    extern __shared__ char smem[];
    const uint32_t sb = smem_u32(smem);
    const int tid = threadIdx.x, wid = tid >> 5, lane = tid & 31;
    const int warp_m = wid >> 1, warp_n = wid & 1;
    const int bn = blockIdx.x * 128, bm = blockIdx.y * 128;

    float acc[2][8][4];
#pragma unroll
    for (int i = 0; i < 2; i++)
#pragma unroll
        for (int j = 0; j < 8; j++)
#pragma unroll
            for (int r = 0; r < 4; r++) acc[i][j][r] = 0.0f;

    load_chunk2(sb, 0, bm, bn);
    CP_COMMIT();

    const int NC = 24;
    for (int c = 0; c < NC; c++) {
        uint32_t cur = sb + (c & 1) * STAGE_B;
        if (c + 1 < NC) {
            load_chunk2(sb + ((c + 1) & 1) * STAGE_B, c + 1, bm, bn);
            CP_COMMIT();
            CP_WAIT(1);
        } else {
            CP_WAIT(0);
        }
        __syncthreads();
        compute_stage(cur, acc, warp_m, warp_n, lane);
        __syncthreads();
    }

    const int rw = lane >> 2, cq = lane & 3;
#pragma unroll
    for (int im = 0; im < 2; im++) {
        int m0 = bm + warp_m * 32 + im * 16 + rw;
#pragma unroll
        for (int jf = 0; jf < 8; jf++) {
            int n = bn + warp_n * 64 + jf * 8 + cq * 2;
            float b0 = bdx[n] + bout[n], b1 = bdx[n + 1] + bout[n + 1];
            float* a4 = acc[im][jf];
            *(float2*)(out + (size_t)m0 * DOUT + n) =
                make_float2(0.5f * (a4[0] + b0), 0.5f * (a4[1] + b1));
            *(float2*)(out + (size_t)(m0 + 8) * DOUT + n) =
                make_float2(0.5f * (a4[2] + b0), 0.5f * (a4[3] + b1));
        }
    }
}

// ---------------------------------------------------------------------------
extern "C" void kernel_launch(void* const* d_in, const int* in_sizes, int n_in,
                              void* d_out, int out_size)
{
    const float* x       = (const float*)d_in[0];
    const float* h0      = (const float*)d_in[1];
    const float* a_logit = (const float*)d_in[2];
    const float* W_dx    = (const float*)d_in[3];
    const float* b_dx    = (const float*)d_in[4];
    const float* W_in    = (const float*)d_in[5];
    const float* b_in    = (const float*)d_in[6];
    const float* W_out   = (const float*)d_in[7];
    const float* b_out   = (const float*)d_in[8];
    float* out = (float*)d_out;

    cudaFuncSetAttribute(gemm_u_mma,   cudaFuncAttributeMaxDynamicSharedMemorySize, SMEM_TOT);
    cudaFuncSetAttribute(gemm_out_mma, cudaFuncAttributeMaxDynamicSharedMemorySize, SMEM_TOT);

    precompute_kernel<<<1, 1024>>>(a_logit);
    convert_x_kernel<<<(int)((size_t)M_ * DIN / 8 / 256), 256>>>(x);
    transpose_all_kernel<<<1280, dim3(32, 8)>>>(W_in, W_dx, W_out);

    gemm_u_mma<<<dim3(DHID / 128, M_ / 128), 256, SMEM_TOT>>>(b_in);

    scan_phaseA<<<dim3(4, NCH, B_), 256>>>();
    scan_phaseB<<<(B_ * DHID) / 256, 256>>>(h0, out);
    scan_phaseC<<<dim3(4, NCH, B_), 256>>>();

    gemm_out_mma<<<dim3(DOUT / 128, M_ / 128), 256, SMEM_TOT>>>(b_dx, b_out, out);
}